// round 15
// baseline (speedup 1.0000x reference)
#include <cuda_runtime.h>
#include <cuda_bf16.h>

#define NN   100000
#define NPAD 100096
#define EMAX 1600000
#define D    64

#define SCAN_CHUNK  512
#define SCAN_BLOCKS ((NN + SCAN_CHUNK - 1) / SCAN_CHUNK)   // 196

#define ST_AGG (1u << 30)
#define ST_INC (2u << 30)
#define ST_VAL 0x00FFFFFFu

typedef unsigned long long ull;

// ---------------- scratch (static device globals; no allocation) ----------------
__device__ float g_buf1[NPAD * D];
__device__ float g_buf2[NPAD * D];
__device__ float g_mean[NPAD * D];
__device__ int   g_csr[EMAX];
__device__ int   g_rowptr[NN + 1];
__device__ int   g_cnt[NN];        // zero-initialized; k_scanapply re-zeroes after use
__device__ int   g_cursor[NN];
__device__ float g_rdeg[NN];
__device__ unsigned g_scanstate[SCAN_BLOCKS];  // zeroed by k_deg each call

// ---------------- helpers ----------------
__device__ __forceinline__ int block_is64(const int* __restrict__ ei32) {
    __shared__ int sh;
    if (threadIdx.x < 32) {
        int v = __ldg(ei32 + 2 * threadIdx.x + 1);
        unsigned m = __ballot_sync(0xffffffffu, v == 0);
        if (threadIdx.x == 0) sh = (m == 0xffffffffu) ? 1 : 0;
    }
    __syncthreads();
    return sh;
}

__device__ __forceinline__ int load_idx(const void* ei, size_t pos, int is64) {
    if (is64) return (int)__ldg((const long long*)ei + pos);
    return __ldg((const int*)ei + pos);
}

// ---------------- CSR build ----------------
__global__ void __launch_bounds__(256) k_deg(const void* __restrict__ ei, int E) {
    int is64 = block_is64((const int*)ei);
    if (blockIdx.x < SCAN_BLOCKS && threadIdx.x == 0) g_scanstate[blockIdx.x] = 0u;
    int e = (blockIdx.x * 256 + threadIdx.x) * 2;
    if (e < E) atomicAdd(&g_cnt[load_idx(ei, (size_t)E + e, is64)], 1);
    if (e + 1 < E) atomicAdd(&g_cnt[load_idx(ei, (size_t)E + e + 1, is64)], 1);
}

// single-pass scan + apply (decoupled lookback). Resets g_cnt for next call.
__global__ void __launch_bounds__(256) k_scanapply() {
    int b = blockIdx.x;
    int t = threadIdx.x;
    int lane = t & 31;
    int w = t >> 5;

    int i0 = b * SCAN_CHUNK + t * 2;
    int c0 = (i0 < NN) ? g_cnt[i0] : 0;
    int c1 = (i0 + 1 < NN) ? g_cnt[i0 + 1] : 0;
    int s = c0 + c1;

    int incl = s;
#pragma unroll
    for (int off = 1; off < 32; off <<= 1) {
        int n = __shfl_up_sync(0xffffffffu, incl, off);
        if (lane >= off) incl += n;
    }
    __shared__ int wsum[8];
    __shared__ int sh_excl;
    if (lane == 31) wsum[w] = incl;
    __syncthreads();

    if (t == 0) {
        int tot = 0;
#pragma unroll
        for (int i = 0; i < 8; i++) tot += wsum[i];
        unsigned pub = ((b == 0) ? ST_INC : ST_AGG) | (unsigned)tot;
        atomicExch(&g_scanstate[b], pub);
    }

    if (w == 0) {
        int excl = 0;
        if (b > 0) {
            int lb = b - 1;
            while (true) {
                int idx = lb - lane;
                unsigned v;
                if (idx < 0) {
                    v = ST_INC;
                } else {
                    volatile unsigned* p = (volatile unsigned*)&g_scanstate[idx];
                    v = *p;
                    while (v == 0u) { __nanosleep(20); v = *p; }
                }
                unsigned st = v & 0xC0000000u;
                int val = (int)(v & ST_VAL);
                unsigned mInc = __ballot_sync(0xffffffffu, st == ST_INC);
                int li = __ffs(mInc) - 1;
                int take = (mInc == 0u) ? 1 : (lane <= li);
                int contrib = take ? val : 0;
#pragma unroll
                for (int off = 16; off; off >>= 1)
                    contrib += __shfl_down_sync(0xffffffffu, contrib, off);
                contrib = __shfl_sync(0xffffffffu, contrib, 0);
                excl += contrib;
                if (mInc) break;
                lb -= 32;
            }
        }
        if (lane == 0) {
            sh_excl = excl;
            int tot = 0;
#pragma unroll
            for (int i = 0; i < 8; i++) tot += wsum[i];
            if (b > 0) atomicExch(&g_scanstate[b], ST_INC | (unsigned)(excl + tot));
            if (b == SCAN_BLOCKS - 1) g_rowptr[NN] = excl + tot;
        }
    }
    __syncthreads();

    int excl = sh_excl;
    int woff = 0;
#pragma unroll
    for (int i = 0; i < 8; i++)
        if (i < w) woff += wsum[i];
    int run = excl + woff + incl - s;

    if (i0 < NN) {
        g_rowptr[i0] = run;
        g_cursor[i0] = run;
        g_rdeg[i0] = 1.0f / (float)max(c0, 1);
        g_cnt[i0] = 0;
        run += c0;
    }
    if (i0 + 1 < NN) {
        g_rowptr[i0 + 1] = run;
        g_cursor[i0 + 1] = run;
        g_rdeg[i0 + 1] = 1.0f / (float)max(c1, 1);
        g_cnt[i0 + 1] = 0;
    }
}

__global__ void __launch_bounds__(256) k_fill(const void* __restrict__ ei, int E) {
    int is64 = block_is64((const int*)ei);
    int e = (blockIdx.x * 256 + threadIdx.x) * 2;
    if (e < E) {
        int src = load_idx(ei, (size_t)e, is64);
        int dst = load_idx(ei, (size_t)E + e, is64);
        g_csr[atomicAdd(&g_cursor[dst], 1)] = src;
    }
    if (e + 1 < E) {
        int src = load_idx(ei, (size_t)e + 1, is64);
        int dst = load_idx(ei, (size_t)E + e + 1, is64);
        g_csr[atomicAdd(&g_cursor[dst], 1)] = src;
    }
}

// ---------------- aggregation: warp per dst node, 16 rows in flight ----------------
__global__ void __launch_bounds__(256) k_agg(const float* __restrict__ xin, int srcsel) {
    const float* h = (srcsel == 0) ? xin : (srcsel == 1) ? g_buf1 : g_buf2;
    int w = blockIdx.x * 8 + (threadIdx.x >> 5);
    if (w >= NN) return;
    int lane = threadIdx.x & 31;
    int sub = lane >> 4;
    int c = lane & 15;
    int beg = g_rowptr[w];
    int end = g_rowptr[w + 1];
    const float4* hp = (const float4*)h;

    float ax0 = 0.f, ay0 = 0.f, az0 = 0.f, aw0 = 0.f;
    float ax1 = 0.f, ay1 = 0.f, az1 = 0.f, aw1 = 0.f;
    int j = beg + sub;
    for (; j + 14 < end; j += 16) {
        int s0 = g_csr[j];
        int s1 = g_csr[j + 2];
        int s2 = g_csr[j + 4];
        int s3 = g_csr[j + 6];
        int s4 = g_csr[j + 8];
        int s5 = g_csr[j + 10];
        int s6 = g_csr[j + 12];
        int s7 = g_csr[j + 14];
        float4 v0 = __ldg(hp + s0 * 16 + c);
        float4 v1 = __ldg(hp + s1 * 16 + c);
        float4 v2 = __ldg(hp + s2 * 16 + c);
        float4 v3 = __ldg(hp + s3 * 16 + c);
        float4 v4 = __ldg(hp + s4 * 16 + c);
        float4 v5 = __ldg(hp + s5 * 16 + c);
        float4 v6 = __ldg(hp + s6 * 16 + c);
        float4 v7 = __ldg(hp + s7 * 16 + c);
        ax0 += v0.x; ay0 += v0.y; az0 += v0.z; aw0 += v0.w;
        ax1 += v1.x; ay1 += v1.y; az1 += v1.z; aw1 += v1.w;
        ax0 += v2.x; ay0 += v2.y; az0 += v2.z; aw0 += v2.w;
        ax1 += v3.x; ay1 += v3.y; az1 += v3.z; aw1 += v3.w;
        ax0 += v4.x; ay0 += v4.y; az0 += v4.z; aw0 += v4.w;
        ax1 += v5.x; ay1 += v5.y; az1 += v5.z; aw1 += v5.w;
        ax0 += v6.x; ay0 += v6.y; az0 += v6.z; aw0 += v6.w;
        ax1 += v7.x; ay1 += v7.y; az1 += v7.z; aw1 += v7.w;
    }
    for (; j < end; j += 2) {
        float4 v = __ldg(hp + g_csr[j] * 16 + c);
        ax0 += v.x; ay0 += v.y; az0 += v.z; aw0 += v.w;
    }
    float x = ax0 + ax1, y = ay0 + ay1, z = az0 + az1, ww = aw0 + aw1;
    x += __shfl_xor_sync(0xffffffffu, x, 16);
    y += __shfl_xor_sync(0xffffffffu, y, 16);
    z += __shfl_xor_sync(0xffffffffu, z, 16);
    ww += __shfl_xor_sync(0xffffffffu, ww, 16);
    if (sub == 0) {
        float rd = g_rdeg[w];
        float4 r;
        r.x = x * rd; r.y = y * rd; r.z = z * rd; r.w = ww * rd;
        ((float4*)g_mean)[w * 16 + c] = r;
    }
}

// ---------------- tensor-core GEMM (3xTF32, ~fp32 precision) ----------------------
// C[128-tile][64] = A[128][64] @ W[64][64], m16n8k8 tf32 mma, big/small operand split.
// 128 threads = 4 warps; warp covers 2 m-tiles (32 nodes) x all 64 cols (8 n-tiles).
// sh_a [node][k] stride 68: a-frag LDS bank = 4*g+tig -> conflict-free.
// W slabs (16 k-rows) as big/small tf32, stride 72: b-frag bank = 8*tig+g -> conflict-free.
// MODE: 0 = dst = srcA@WA + bias ; 1 = dst += mean@WA (opt relu) ;
//       2 = dst = srcA@WA + mean@WB + bias (opt relu)
__device__ __forceinline__ unsigned tf32_of(float f) {
    unsigned r;
    asm("cvt.rna.tf32.f32 %0, %1;" : "=r"(r) : "f"(f));
    return r;
}

__device__ __forceinline__ void mma_tf32(float* c, unsigned a0, unsigned a1,
                                         unsigned a2, unsigned a3,
                                         unsigned b0, unsigned b1) {
    asm("mma.sync.aligned.m16n8k8.row.col.f32.tf32.tf32.f32 "
        "{%0,%1,%2,%3}, {%4,%5,%6,%7}, {%8,%9}, {%0,%1,%2,%3};"
        : "+f"(c[0]), "+f"(c[1]), "+f"(c[2]), "+f"(c[3])
        : "r"(a0), "r"(a1), "r"(a2), "r"(a3), "r"(b0), "r"(b1));
}

template <int MODE, bool RELU>
__global__ void __launch_bounds__(128) k_gemm_tc(const float* __restrict__ xin,
                                                 const float* __restrict__ WA,
                                                 const float* __restrict__ WB,
                                                 const float* __restrict__ bias,
                                                 float* __restrict__ outp,
                                                 int srcsel, int dstsel) {
    __shared__ float    sh_a[128 * 68];   // 34816 B
    __shared__ unsigned sh_wb[16 * 72];   //  4608 B (tf32 big)
    __shared__ unsigned sh_ws[16 * 72];   //  4608 B (tf32 small)

    const float* srcA = (srcsel == 0) ? xin : (srcsel == 1) ? g_buf1 : g_buf2;
    float* out = (dstsel == 0) ? outp : (dstsel == 1) ? g_buf1 : g_buf2;

    int t = threadIdx.x;
    int warp = t >> 5;
    int lane = t & 31;
    int g = lane >> 2;     // 0..7
    int tig = lane & 3;    // 0..3
    int base = blockIdx.x * 128;

    float C[2][8][4];
#pragma unroll
    for (int mt = 0; mt < 2; mt++)
#pragma unroll
        for (int nt = 0; nt < 8; nt++)
#pragma unroll
            for (int i = 0; i < 4; i++) C[mt][nt][i] = 0.f;

    const int NPH = (MODE == 2) ? 2 : 1;
    for (int ph = 0; ph < NPH; ph++) {
        const float* src = (MODE == 1) ? g_mean : ((ph == 0) ? srcA : g_mean);
        const float* W = (ph == 0) ? WA : WB;
        if (ph) __syncthreads();   // phase-0 reads done before restaging

        // stage A tile: 128 rows x 16 float4
#pragma unroll
        for (int it = 0; it < 16; it++) {
            int idx = t + it * 128;
            int row = idx >> 4;
            int c4 = idx & 15;
            float4 v = make_float4(0.f, 0.f, 0.f, 0.f);
            if (base + row < NN)
                v = ((const float4*)(src + (size_t)(base + row) * 64))[c4];
            *(float4*)(sh_a + row * 68 + c4 * 4) = v;
        }

#pragma unroll 1
        for (int kb = 0; kb < 4; kb++) {
            int kb16 = kb * 16;
            __syncthreads();   // A staged / previous slab reads done
            // stage W slab (16 rows), converted to big/small tf32
#pragma unroll
            for (int it = 0; it < 2; it++) {
                int idx = t + it * 128;
                int r = idx >> 4;
                int c4 = idx & 15;
                float4 wv = ((const float4*)(W + (size_t)(kb16 + r) * 64))[c4];
                uint4 bg, sm;
                bg.x = tf32_of(wv.x); sm.x = tf32_of(wv.x - __uint_as_float(bg.x));
                bg.y = tf32_of(wv.y); sm.y = tf32_of(wv.y - __uint_as_float(bg.y));
                bg.z = tf32_of(wv.z); sm.z = tf32_of(wv.z - __uint_as_float(bg.z));
                bg.w = tf32_of(wv.w); sm.w = tf32_of(wv.w - __uint_as_float(bg.w));
                *(uint4*)(sh_wb + r * 72 + c4 * 4) = bg;
                *(uint4*)(sh_ws + r * 72 + c4 * 4) = sm;
            }
            __syncthreads();

#pragma unroll
            for (int ks = 0; ks < 2; ks++) {
                int kcol = kb16 + ks * 8 + tig;
                unsigned ab[2][4], as[2][4];
#pragma unroll
                for (int mt = 0; mt < 2; mt++) {
                    int r0 = warp * 32 + mt * 16 + g;
                    float f0 = sh_a[r0 * 68 + kcol];
                    float f1 = sh_a[(r0 + 8) * 68 + kcol];
                    float f2 = sh_a[r0 * 68 + kcol + 4];
                    float f3 = sh_a[(r0 + 8) * 68 + kcol + 4];
                    ab[mt][0] = tf32_of(f0); as[mt][0] = tf32_of(f0 - __uint_as_float(ab[mt][0]));
                    ab[mt][1] = tf32_of(f1); as[mt][1] = tf32_of(f1 - __uint_as_float(ab[mt][1]));
                    ab[mt][2] = tf32_of(f2); as[mt][2] = tf32_of(f2 - __uint_as_float(ab[mt][2]));
                    ab[mt][3] = tf32_of(f3); as[mt][3] = tf32_of(f3 - __uint_as_float(ab[mt][3]));
                }
                int krow = ks * 8 + tig;
#pragma unroll
                for (int nt = 0; nt < 8; nt++) {
                    unsigned b0b = sh_wb[krow * 72 + nt * 8 + g];
                    unsigned b1b = sh_wb[(krow + 4) * 72 + nt * 8 + g];
                    unsigned b0s = sh_ws[krow * 72 + nt * 8 + g];
                    unsigned b1s = sh_ws[(krow + 4) * 72 + nt * 8 + g];
#pragma unroll
                    for (int mt = 0; mt < 2; mt++) {
                        mma_tf32(C[mt][nt], ab[mt][0], ab[mt][1], ab[mt][2], ab[mt][3], b0b, b1b);
                        mma_tf32(C[mt][nt], as[mt][0], as[mt][1], as[mt][2], as[mt][3], b0b, b1b);
                        mma_tf32(C[mt][nt], ab[mt][0], ab[mt][1], ab[mt][2], ab[mt][3], b0s, b1s);
                    }
                }
            }
        }
    }

    // epilogue: C[mt][nt][{0,1}] -> row g, cols n0,n0+1 ; [{2,3}] -> row g+8
#pragma unroll
    for (int mt = 0; mt < 2; mt++) {
        int rowA = base + warp * 32 + mt * 16 + g;
        int rowB = rowA + 8;
#pragma unroll
        for (int nt = 0; nt < 8; nt++) {
            int n0 = nt * 8 + tig * 2;
            float b0 = 0.f, b1 = 0.f;
            if (MODE != 1) { b0 = __ldg(bias + n0); b1 = __ldg(bias + n0 + 1); }
            if (rowA < NN) {
                float v0 = C[mt][nt][0], v1 = C[mt][nt][1];
                if (MODE == 1) {
                    float2 pv = *(const float2*)(out + (size_t)rowA * 64 + n0);
                    v0 += pv.x; v1 += pv.y;
                } else { v0 += b0; v1 += b1; }
                if (RELU) { v0 = fmaxf(v0, 0.f); v1 = fmaxf(v1, 0.f); }
                float2 o; o.x = v0; o.y = v1;
                *(float2*)(out + (size_t)rowA * 64 + n0) = o;
            }
            if (rowB < NN) {
                float v0 = C[mt][nt][2], v1 = C[mt][nt][3];
                if (MODE == 1) {
                    float2 pv = *(const float2*)(out + (size_t)rowB * 64 + n0);
                    v0 += pv.x; v1 += pv.y;
                } else { v0 += b0; v1 += b1; }
                if (RELU) { v0 = fmaxf(v0, 0.f); v1 = fmaxf(v1, 0.f); }
                float2 o; o.x = v0; o.y = v1;
                *(float2*)(out + (size_t)rowB * 64 + n0) = o;
            }
        }
    }
}

// ---------------- launch: kernel launches ONLY (graph-capture safe) ----------------
extern "C" void kernel_launch(void* const* d_in, const int* in_sizes, int n_in,
                              void* d_out, int out_size) {
    const float* x = (const float*)d_in[0];
    const void* ei = d_in[1];
    const float* ws1 = (const float*)d_in[2];
    const float* wn1 = (const float*)d_in[3];
    const float* b1  = (const float*)d_in[4];
    const float* ws2 = (const float*)d_in[5];
    const float* wn2 = (const float*)d_in[6];
    const float* b2  = (const float*)d_in[7];
    const float* ws3 = (const float*)d_in[8];
    const float* wn3 = (const float*)d_in[9];
    const float* b3  = (const float*)d_in[10];
    float* out = (float*)d_out;

    int E = in_sizes[1] / 2;

    int eb2 = (E / 2 + 255) / 256;
    int aggBlocks = (NN + 7) / 8;
    int gemmBlocks = (NN + 127) / 128;   // 782

    // CSR build
    k_deg<<<eb2, 256>>>(ei, E);
    k_scanapply<<<SCAN_BLOCKS, 256>>>();
    k_fill<<<eb2, 256>>>(ei, E);

    // layer 1 (split: TC self-GEMM at profiled index 3)
    k_gemm_tc<0, false><<<gemmBlocks, 128>>>(x, ws1, ws1, b1, out, 0, 1);  // buf1 = x@Ws1+b1
    k_agg<<<aggBlocks, 256>>>(x, 0);                                        // mean(x)
    k_gemm_tc<1, true><<<gemmBlocks, 128>>>(x, wn1, wn1, b1, out, 0, 1);    // buf1 += mean@Wn1; relu

    // layer 2 (fused dual)
    k_agg<<<aggBlocks, 256>>>(x, 1);                                        // mean(buf1)
    k_gemm_tc<2, true><<<gemmBlocks, 128>>>(x, ws2, wn2, b2, out, 1, 2);    // buf2; relu

    // layer 3 (fused dual, no relu)
    k_agg<<<aggBlocks, 256>>>(x, 2);                                        // mean(buf2)
    k_gemm_tc<2, false><<<gemmBlocks, 128>>>(x, ws3, wn3, b3, out, 2, 0);   // out
}

// round 16
// speedup vs baseline: 1.4694x; 1.4694x over previous
#include <cuda_runtime.h>
#include <cuda_bf16.h>

#define NN   100000
#define NPAD 100096
#define EMAX 1600000
#define D    64

#define SCAN_CHUNK  512
#define SCAN_BLOCKS ((NN + SCAN_CHUNK - 1) / SCAN_CHUNK)   // 196

#define ST_AGG (1u << 30)
#define ST_INC (2u << 30)
#define ST_VAL 0x00FFFFFFu

typedef unsigned long long ull;

// ---------------- scratch (static device globals; no allocation) ----------------
__device__ float g_buf1[NPAD * D];
__device__ float g_buf2[NPAD * D];
__device__ float g_mean[NPAD * D];
__device__ int   g_csr[EMAX];
__device__ int   g_rowptr[NN + 1];
__device__ int   g_cnt[NN];        // zero-initialized; k_scanapply re-zeroes after use
__device__ int   g_cursor[NN];
__device__ float g_rdeg[NN];
__device__ unsigned g_scanstate[SCAN_BLOCKS];  // zeroed by k_deg each call

// ---------------- helpers ----------------
__device__ __forceinline__ int block_is64(const int* __restrict__ ei32) {
    __shared__ int sh;
    if (threadIdx.x < 32) {
        int v = __ldg(ei32 + 2 * threadIdx.x + 1);
        unsigned m = __ballot_sync(0xffffffffu, v == 0);
        if (threadIdx.x == 0) sh = (m == 0xffffffffu) ? 1 : 0;
    }
    __syncthreads();
    return sh;
}

__device__ __forceinline__ int load_idx(const void* ei, size_t pos, int is64) {
    if (is64) return (int)__ldg((const long long*)ei + pos);
    return __ldg((const int*)ei + pos);
}

// ---------------- CSR build ----------------
__global__ void __launch_bounds__(256) k_deg(const void* __restrict__ ei, int E) {
    int is64 = block_is64((const int*)ei);
    if (blockIdx.x < SCAN_BLOCKS && threadIdx.x == 0) g_scanstate[blockIdx.x] = 0u;
    int e = (blockIdx.x * 256 + threadIdx.x) * 2;
    if (e < E) atomicAdd(&g_cnt[load_idx(ei, (size_t)E + e, is64)], 1);
    if (e + 1 < E) atomicAdd(&g_cnt[load_idx(ei, (size_t)E + e + 1, is64)], 1);
}

// single-pass scan + apply (decoupled lookback). Resets g_cnt for next call.
__global__ void __launch_bounds__(256) k_scanapply() {
    int b = blockIdx.x;
    int t = threadIdx.x;
    int lane = t & 31;
    int w = t >> 5;

    int i0 = b * SCAN_CHUNK + t * 2;
    int c0 = (i0 < NN) ? g_cnt[i0] : 0;
    int c1 = (i0 + 1 < NN) ? g_cnt[i0 + 1] : 0;
    int s = c0 + c1;

    int incl = s;
#pragma unroll
    for (int off = 1; off < 32; off <<= 1) {
        int n = __shfl_up_sync(0xffffffffu, incl, off);
        if (lane >= off) incl += n;
    }
    __shared__ int wsum[8];
    __shared__ int sh_excl;
    if (lane == 31) wsum[w] = incl;
    __syncthreads();

    if (t == 0) {
        int tot = 0;
#pragma unroll
        for (int i = 0; i < 8; i++) tot += wsum[i];
        unsigned pub = ((b == 0) ? ST_INC : ST_AGG) | (unsigned)tot;
        atomicExch(&g_scanstate[b], pub);
    }

    if (w == 0) {
        int excl = 0;
        if (b > 0) {
            int lb = b - 1;
            while (true) {
                int idx = lb - lane;
                unsigned v;
                if (idx < 0) {
                    v = ST_INC;
                } else {
                    volatile unsigned* p = (volatile unsigned*)&g_scanstate[idx];
                    v = *p;
                    while (v == 0u) { __nanosleep(20); v = *p; }
                }
                unsigned st = v & 0xC0000000u;
                int val = (int)(v & ST_VAL);
                unsigned mInc = __ballot_sync(0xffffffffu, st == ST_INC);
                int li = __ffs(mInc) - 1;
                int take = (mInc == 0u) ? 1 : (lane <= li);
                int contrib = take ? val : 0;
#pragma unroll
                for (int off = 16; off; off >>= 1)
                    contrib += __shfl_down_sync(0xffffffffu, contrib, off);
                contrib = __shfl_sync(0xffffffffu, contrib, 0);
                excl += contrib;
                if (mInc) break;
                lb -= 32;
            }
        }
        if (lane == 0) {
            sh_excl = excl;
            int tot = 0;
#pragma unroll
            for (int i = 0; i < 8; i++) tot += wsum[i];
            if (b > 0) atomicExch(&g_scanstate[b], ST_INC | (unsigned)(excl + tot));
            if (b == SCAN_BLOCKS - 1) g_rowptr[NN] = excl + tot;
        }
    }
    __syncthreads();

    int excl = sh_excl;
    int woff = 0;
#pragma unroll
    for (int i = 0; i < 8; i++)
        if (i < w) woff += wsum[i];
    int run = excl + woff + incl - s;

    if (i0 < NN) {
        g_rowptr[i0] = run;
        g_cursor[i0] = run;
        g_rdeg[i0] = 1.0f / (float)max(c0, 1);
        g_cnt[i0] = 0;
        run += c0;
    }
    if (i0 + 1 < NN) {
        g_rowptr[i0 + 1] = run;
        g_cursor[i0 + 1] = run;
        g_rdeg[i0 + 1] = 1.0f / (float)max(c1, 1);
        g_cnt[i0 + 1] = 0;
    }
}

__global__ void __launch_bounds__(256) k_fill(const void* __restrict__ ei, int E) {
    int is64 = block_is64((const int*)ei);
    int e = (blockIdx.x * 256 + threadIdx.x) * 2;
    if (e < E) {
        int src = load_idx(ei, (size_t)e, is64);
        int dst = load_idx(ei, (size_t)E + e, is64);
        g_csr[atomicAdd(&g_cursor[dst], 1)] = src;
    }
    if (e + 1 < E) {
        int src = load_idx(ei, (size_t)e + 1, is64);
        int dst = load_idx(ei, (size_t)E + e + 1, is64);
        g_csr[atomicAdd(&g_cursor[dst], 1)] = src;
    }
}

// ---------------- aggregation: warp per dst node, 16 rows in flight ----------------
__global__ void __launch_bounds__(256) k_agg(const float* __restrict__ xin, int srcsel) {
    const float* h = (srcsel == 0) ? xin : (srcsel == 1) ? g_buf1 : g_buf2;
    int w = blockIdx.x * 8 + (threadIdx.x >> 5);
    if (w >= NN) return;
    int lane = threadIdx.x & 31;
    int sub = lane >> 4;
    int c = lane & 15;
    int beg = g_rowptr[w];
    int end = g_rowptr[w + 1];
    const float4* hp = (const float4*)h;

    float ax0 = 0.f, ay0 = 0.f, az0 = 0.f, aw0 = 0.f;
    float ax1 = 0.f, ay1 = 0.f, az1 = 0.f, aw1 = 0.f;
    int j = beg + sub;
    for (; j + 14 < end; j += 16) {
        int s0 = g_csr[j];
        int s1 = g_csr[j + 2];
        int s2 = g_csr[j + 4];
        int s3 = g_csr[j + 6];
        int s4 = g_csr[j + 8];
        int s5 = g_csr[j + 10];
        int s6 = g_csr[j + 12];
        int s7 = g_csr[j + 14];
        float4 v0 = __ldg(hp + s0 * 16 + c);
        float4 v1 = __ldg(hp + s1 * 16 + c);
        float4 v2 = __ldg(hp + s2 * 16 + c);
        float4 v3 = __ldg(hp + s3 * 16 + c);
        float4 v4 = __ldg(hp + s4 * 16 + c);
        float4 v5 = __ldg(hp + s5 * 16 + c);
        float4 v6 = __ldg(hp + s6 * 16 + c);
        float4 v7 = __ldg(hp + s7 * 16 + c);
        ax0 += v0.x; ay0 += v0.y; az0 += v0.z; aw0 += v0.w;
        ax1 += v1.x; ay1 += v1.y; az1 += v1.z; aw1 += v1.w;
        ax0 += v2.x; ay0 += v2.y; az0 += v2.z; aw0 += v2.w;
        ax1 += v3.x; ay1 += v3.y; az1 += v3.z; aw1 += v3.w;
        ax0 += v4.x; ay0 += v4.y; az0 += v4.z; aw0 += v4.w;
        ax1 += v5.x; ay1 += v5.y; az1 += v5.z; aw1 += v5.w;
        ax0 += v6.x; ay0 += v6.y; az0 += v6.z; aw0 += v6.w;
        ax1 += v7.x; ay1 += v7.y; az1 += v7.z; aw1 += v7.w;
    }
    for (; j < end; j += 2) {
        float4 v = __ldg(hp + g_csr[j] * 16 + c);
        ax0 += v.x; ay0 += v.y; az0 += v.z; aw0 += v.w;
    }
    float x = ax0 + ax1, y = ay0 + ay1, z = az0 + az1, ww = aw0 + aw1;
    x += __shfl_xor_sync(0xffffffffu, x, 16);
    y += __shfl_xor_sync(0xffffffffu, y, 16);
    z += __shfl_xor_sync(0xffffffffu, z, 16);
    ww += __shfl_xor_sync(0xffffffffu, ww, 16);
    if (sub == 0) {
        float rd = g_rdeg[w];
        float4 r;
        r.x = x * rd; r.y = y * rd; r.z = z * rd; r.w = ww * rd;
        ((float4*)g_mean)[w * 16 + c] = r;
    }
}

// ---------------- fused dual tensor-core GEMM (3xTF32, ~fp32 precision) -----------
// dst = srcA@WA + mean@WB + bias (opt relu).
// 128-node tile, 256 threads = 8 warps; warp = one m16 tile x all 64 cols (8 n-tiles).
// sh_a [node][k] stride 68: a-frag LDS bank = 4*g+tig -> conflict-free.
// W slabs (16 k-rows) big/small tf32, stride 72: b-frag bank = 8*tig+g -> conflict-free.
__device__ __forceinline__ unsigned tf32_of(float f) {
    unsigned r;
    asm("cvt.rna.tf32.f32 %0, %1;" : "=r"(r) : "f"(f));
    return r;
}

__device__ __forceinline__ void mma_tf32(float* c, unsigned a0, unsigned a1,
                                         unsigned a2, unsigned a3,
                                         unsigned b0, unsigned b1) {
    asm("mma.sync.aligned.m16n8k8.row.col.f32.tf32.tf32.f32 "
        "{%0,%1,%2,%3}, {%4,%5,%6,%7}, {%8,%9}, {%0,%1,%2,%3};"
        : "+f"(c[0]), "+f"(c[1]), "+f"(c[2]), "+f"(c[3])
        : "r"(a0), "r"(a1), "r"(a2), "r"(a3), "r"(b0), "r"(b1));
}

template <bool RELU>
__global__ void __launch_bounds__(256) k_gemm_tc(const float* __restrict__ xin,
                                                 const float* __restrict__ WA,
                                                 const float* __restrict__ WB,
                                                 const float* __restrict__ bias,
                                                 float* __restrict__ outp,
                                                 int srcsel, int dstsel) {
    __shared__ float    sh_a[128 * 68];   // 34816 B
    __shared__ unsigned sh_wb[16 * 72];   //  4608 B (tf32 big)
    __shared__ unsigned sh_ws[16 * 72];   //  4608 B (tf32 small)

    const float* srcA = (srcsel == 0) ? xin : (srcsel == 1) ? g_buf1 : g_buf2;
    float* out = (dstsel == 0) ? outp : (dstsel == 1) ? g_buf1 : g_buf2;

    int t = threadIdx.x;
    int warp = t >> 5;     // 0..7 -> m16 tile
    int lane = t & 31;
    int g = lane >> 2;     // 0..7
    int tig = lane & 3;    // 0..3
    int base = blockIdx.x * 128;

    float C[8][4];
#pragma unroll
    for (int nt = 0; nt < 8; nt++)
#pragma unroll
        for (int i = 0; i < 4; i++) C[nt][i] = 0.f;

    for (int ph = 0; ph < 2; ph++) {
        const float* src = (ph == 0) ? srcA : g_mean;
        const float* W = (ph == 0) ? WA : WB;
        if (ph) __syncthreads();   // phase-0 reads done before restaging

        // stage A tile: 128 rows x 16 float4 (2048 / 256 threads = 8 iters)
#pragma unroll
        for (int it = 0; it < 8; it++) {
            int idx = t + it * 256;
            int row = idx >> 4;
            int c4 = idx & 15;
            float4 v = make_float4(0.f, 0.f, 0.f, 0.f);
            if (base + row < NN)
                v = ((const float4*)(src + (size_t)(base + row) * 64))[c4];
            *(float4*)(sh_a + row * 68 + c4 * 4) = v;
        }

#pragma unroll 1
        for (int kb = 0; kb < 4; kb++) {
            int kb16 = kb * 16;
            __syncthreads();   // A staged / previous slab reads done
            // stage W slab (16 rows x 16 float4 = 256 = one full pass)
            {
                int r = t >> 4;
                int c4 = t & 15;
                float4 wv = ((const float4*)(W + (size_t)(kb16 + r) * 64))[c4];
                uint4 bg, sm;
                bg.x = tf32_of(wv.x); sm.x = tf32_of(wv.x - __uint_as_float(bg.x));
                bg.y = tf32_of(wv.y); sm.y = tf32_of(wv.y - __uint_as_float(bg.y));
                bg.z = tf32_of(wv.z); sm.z = tf32_of(wv.z - __uint_as_float(bg.z));
                bg.w = tf32_of(wv.w); sm.w = tf32_of(wv.w - __uint_as_float(bg.w));
                *(uint4*)(sh_wb + r * 72 + c4 * 4) = bg;
                *(uint4*)(sh_ws + r * 72 + c4 * 4) = sm;
            }
            __syncthreads();

#pragma unroll
            for (int ks = 0; ks < 2; ks++) {
                int kcol = kb16 + ks * 8 + tig;
                int r0 = warp * 16 + g;
                float f0 = sh_a[r0 * 68 + kcol];
                float f1 = sh_a[(r0 + 8) * 68 + kcol];
                float f2 = sh_a[r0 * 68 + kcol + 4];
                float f3 = sh_a[(r0 + 8) * 68 + kcol + 4];
                unsigned ab0 = tf32_of(f0), as0 = tf32_of(f0 - __uint_as_float(ab0));
                unsigned ab1 = tf32_of(f1), as1 = tf32_of(f1 - __uint_as_float(ab1));
                unsigned ab2 = tf32_of(f2), as2 = tf32_of(f2 - __uint_as_float(ab2));
                unsigned ab3 = tf32_of(f3), as3 = tf32_of(f3 - __uint_as_float(ab3));
                int krow = ks * 8 + tig;
#pragma unroll
                for (int nt = 0; nt < 8; nt++) {
                    unsigned b0b = sh_wb[krow * 72 + nt * 8 + g];
                    unsigned b1b = sh_wb[(krow + 4) * 72 + nt * 8 + g];
                    unsigned b0s = sh_ws[krow * 72 + nt * 8 + g];
                    unsigned b1s = sh_ws[(krow + 4) * 72 + nt * 8 + g];
                    mma_tf32(C[nt], ab0, ab1, ab2, ab3, b0b, b1b);
                    mma_tf32(C[nt], as0, as1, as2, as3, b0b, b1b);
                    mma_tf32(C[nt], ab0, ab1, ab2, ab3, b0s, b1s);
                }
            }
        }
    }

    // epilogue: C[nt][{0,1}] -> row g, cols n0,n0+1 ; [{2,3}] -> row g+8
    int rowA = base + warp * 16 + g;
    int rowB = rowA + 8;
#pragma unroll
    for (int nt = 0; nt < 8; nt++) {
        int n0 = nt * 8 + tig * 2;
        float b0 = __ldg(bias + n0);
        float b1 = __ldg(bias + n0 + 1);
        if (rowA < NN) {
            float v0 = C[nt][0] + b0, v1 = C[nt][1] + b1;
            if (RELU) { v0 = fmaxf(v0, 0.f); v1 = fmaxf(v1, 0.f); }
            float2 o; o.x = v0; o.y = v1;
            *(float2*)(out + (size_t)rowA * 64 + n0) = o;
        }
        if (rowB < NN) {
            float v0 = C[nt][2] + b0, v1 = C[nt][3] + b1;
            if (RELU) { v0 = fmaxf(v0, 0.f); v1 = fmaxf(v1, 0.f); }
            float2 o; o.x = v0; o.y = v1;
            *(float2*)(out + (size_t)rowB * 64 + n0) = o;
        }
    }
}

// ---------------- launch: kernel launches ONLY (graph-capture safe) ----------------
extern "C" void kernel_launch(void* const* d_in, const int* in_sizes, int n_in,
                              void* d_out, int out_size) {
    const float* x = (const float*)d_in[0];
    const void* ei = d_in[1];
    const float* ws1 = (const float*)d_in[2];
    const float* wn1 = (const float*)d_in[3];
    const float* b1  = (const float*)d_in[4];
    const float* ws2 = (const float*)d_in[5];
    const float* wn2 = (const float*)d_in[6];
    const float* b2  = (const float*)d_in[7];
    const float* ws3 = (const float*)d_in[8];
    const float* wn3 = (const float*)d_in[9];
    const float* b3  = (const float*)d_in[10];
    float* out = (float*)d_out;

    int E = in_sizes[1] / 2;

    int eb2 = (E / 2 + 255) / 256;
    int aggBlocks = (NN + 7) / 8;
    int gemmBlocks = (NN + 127) / 128;   // 782

    // CSR build
    k_deg<<<eb2, 256>>>(ei, E);
    k_scanapply<<<SCAN_BLOCKS, 256>>>();
    k_fill<<<eb2, 256>>>(ei, E);

    // layer 1: mean(x) then fused dual TC GEMM
    k_agg<<<aggBlocks, 256>>>(x, 0);                                      // mean(x)
    k_gemm_tc<true><<<gemmBlocks, 256>>>(x, ws1, wn1, b1, out, 0, 1);     // buf1; relu

    // layer 2
    k_agg<<<aggBlocks, 256>>>(x, 1);                                      // mean(buf1)
    k_gemm_tc<true><<<gemmBlocks, 256>>>(x, ws2, wn2, b2, out, 1, 2);     // buf2; relu

    // layer 3 (no relu)
    k_agg<<<aggBlocks, 256>>>(x, 2);                                      // mean(buf2)
    k_gemm_tc<false><<<gemmBlocks, 256>>>(x, ws3, wn3, b3, out, 2, 0);    // out
}